// round 4
// baseline (speedup 1.0000x reference)
#include <cuda_runtime.h>
#include <cuda_bf16.h>

#define N_NODES 50000
#define N_EDGES 1600000
#define F_HID   240
#define F_OUT   80

// ---------------- scratch (device globals; no allocation allowed) ----------
__device__ float g_deg[N_NODES];
__device__ float g_dis[N_NODES];
__device__ int   g_cnt[N_NODES];
__device__ int   g_off[N_NODES];
__device__ int   g_cur[N_NODES];
__device__ int   g_src[N_EDGES];
__device__ float g_nrm[N_EDGES];
__device__ float g_bufA[(size_t)N_NODES * F_HID];   // GEMM outputs (pre-agg)
__device__ float g_bufB[(size_t)N_NODES * F_HID];   // agg outputs (post-relu)

// ---------------- graph preprocessing --------------------------------------
__global__ void zero_kernel() {
    int i = blockIdx.x * blockDim.x + threadIdx.x;
    if (i < N_NODES) { g_deg[i] = 0.0f; g_cnt[i] = 0; }
}

__global__ void deg_kernel(const int* __restrict__ ei,
                           const float* __restrict__ ew) {
    int e = blockIdx.x * blockDim.x + threadIdx.x;
    if (e < N_EDGES) {
        int c = ei[N_EDGES + e];
        if ((unsigned)c < N_NODES) {
            atomicAdd(&g_deg[c], ew[e]);
            atomicAdd(&g_cnt[c], 1);
        }
    }
}

__global__ void dis_kernel() {
    int i = blockIdx.x * blockDim.x + threadIdx.x;
    if (i < N_NODES) g_dis[i] = rsqrtf(g_deg[i] + 1.0f);  // +1 = self loop
}

// single-block scan of g_cnt -> g_off (exclusive), also init g_cur
__global__ void scan_kernel() {
    __shared__ int s[1024];
    const int CH = (N_NODES + 1023) / 1024;  // 49
    int t = threadIdx.x;
    int lo = t * CH, hi = min(lo + CH, N_NODES);
    int sum = 0;
    for (int i = lo; i < hi; i++) sum += g_cnt[i];
    s[t] = sum;
    __syncthreads();
    for (int d = 1; d < 1024; d <<= 1) {
        int v = (t >= d) ? s[t - d] : 0;
        __syncthreads();
        s[t] += v;
        __syncthreads();
    }
    int run = (t == 0) ? 0 : s[t - 1];
    for (int i = lo; i < hi; i++) {
        g_off[i] = run; g_cur[i] = run;
        run += g_cnt[i];
    }
}

__global__ void fill_kernel(const int* __restrict__ ei,
                            const float* __restrict__ ew) {
    int e = blockIdx.x * blockDim.x + threadIdx.x;
    if (e < N_EDGES) {
        int r = ei[e];
        int c = ei[N_EDGES + e];
        if ((unsigned)r < N_NODES && (unsigned)c < N_NODES) {
            float nrm = g_dis[r] * ew[e] * g_dis[c];
            int p = atomicAdd(&g_cur[c], 1);
            g_src[p] = r;
            g_nrm[p] = nrm;
        }
    }
}

// ---------------- GEMM1: [N,5] @ [5,240] -> g_bufA -------------------------
__global__ void gemm1_kernel(const float* __restrict__ x,
                             const float* __restrict__ W1) {
    int idx = blockIdx.x * blockDim.x + threadIdx.x;
    if (idx >= N_NODES * F_HID) return;
    int n = idx / F_HID, f = idx - n * F_HID;
    const float* xr = x + n * 5;
    float acc = 0.0f;
#pragma unroll
    for (int k = 0; k < 5; k++) acc = fmaf(xr[k], W1[k * F_HID + f], acc);
    g_bufA[idx] = acc;
}

// ---------------- scatter-max aggregation (CSR by destination) -------------
// Fixed dataflow: ALWAYS reads g_bufA (pre-agg features from a GEMM) and
// writes g_bufB (relu(agg + bias)). One block (256 thr) per node.
__global__ void agg_kernel(const float* __restrict__ bias) {
    const float* __restrict__ h   = g_bufA;
    float* __restrict__       out = g_bufB;
    int n = blockIdx.x;
    int tid = threadIdx.x;
    __shared__ int   s_src[256];
    __shared__ float s_nrm[256];

    float d = g_dis[n];
    int start = g_off[n];
    int cnt   = g_cnt[n];

    float v = 0.0f;
    if (tid < F_HID) v = d * d * h[(size_t)n * F_HID + tid];  // self loop term

    for (int base = 0; base < cnt; base += 256) {
        int m = min(256, cnt - base);
        __syncthreads();
        if (tid < m) {
            s_src[tid] = g_src[start + base + tid];
            s_nrm[tid] = g_nrm[start + base + tid];
        }
        __syncthreads();
        if (tid < F_HID) {
            int e = 0;
            for (; e + 3 < m; e += 4) {
                float a0 = s_nrm[e + 0] * h[(size_t)s_src[e + 0] * F_HID + tid];
                float a1 = s_nrm[e + 1] * h[(size_t)s_src[e + 1] * F_HID + tid];
                float a2 = s_nrm[e + 2] * h[(size_t)s_src[e + 2] * F_HID + tid];
                float a3 = s_nrm[e + 3] * h[(size_t)s_src[e + 3] * F_HID + tid];
                v = fmaxf(v, fmaxf(fmaxf(a0, a1), fmaxf(a2, a3)));
            }
            for (; e < m; e++)
                v = fmaxf(v, s_nrm[e] * h[(size_t)s_src[e] * F_HID + tid]);
        }
    }
    if (tid < F_HID)
        out[(size_t)n * F_HID + tid] = fmaxf(v + bias[tid], 0.0f);  // +b, relu
}

// ---------------- tiled SGEMM: C[M,Nn] = g_bufB[M,K] @ B[K,Nn] (+bias) -----
// BM=128, BN=80, BK=16, 256 threads, 8x5 micro-tile
// A is ALWAYS g_bufB (post-agg features); DST selects g_bufA vs harness out.
template <int DST>  // 0: C = g_bufA ; 1: C = Cout (harness output)
__global__ void gemm_kernel(const float* __restrict__ B,
                            const float* __restrict__ bias,
                            float* __restrict__ Cout,
                            int M, int Nn, int K) {
    const float* __restrict__ A = g_bufB;
    float* __restrict__ C = DST == 0 ? g_bufA : Cout;

    __shared__ float As[16][129];
    __shared__ float Bs[16][80];

    int tid = threadIdx.x;
    int ty = tid / 16, tx = tid % 16;
    int m0 = blockIdx.x * 128;
    int n0 = blockIdx.y * 80;

    float acc[8][5];
#pragma unroll
    for (int i = 0; i < 8; i++)
#pragma unroll
        for (int j = 0; j < 5; j++) acc[i][j] = 0.0f;

    for (int k0 = 0; k0 < K; k0 += 16) {
#pragma unroll
        for (int i = 0; i < 8; i++) {
            int l = tid + i * 256;        // 0..2047
            int r = l >> 4, c = l & 15;
            int row = m0 + r;
            row = row < M ? row : M - 1;
            As[c][r] = A[(size_t)row * K + k0 + c];
        }
#pragma unroll
        for (int i = 0; i < 5; i++) {
            int l = tid + i * 256;        // 0..1279
            int r = l / 80, c = l - r * 80;
            Bs[r][c] = B[(size_t)(k0 + r) * Nn + n0 + c];
        }
        __syncthreads();
#pragma unroll
        for (int kk = 0; kk < 16; kk++) {
            float a[8], b[5];
#pragma unroll
            for (int i = 0; i < 8; i++) a[i] = As[kk][ty * 8 + i];
#pragma unroll
            for (int j = 0; j < 5; j++) b[j] = Bs[kk][tx * 5 + j];
#pragma unroll
            for (int i = 0; i < 8; i++)
#pragma unroll
                for (int j = 0; j < 5; j++) acc[i][j] = fmaf(a[i], b[j], acc[i][j]);
        }
        __syncthreads();
    }

#pragma unroll
    for (int i = 0; i < 8; i++) {
        int row = m0 + ty * 8 + i;
        if (row < M) {
#pragma unroll
            for (int j = 0; j < 5; j++) {
                int col = n0 + tx * 5 + j;
                float v = acc[i][j];
                if (bias) v += bias[col];
                C[(size_t)row * Nn + col] = v;
            }
        }
    }
}

// ---------------- launch ----------------------------------------------------
// Dataflow (ping-pong, both agg calls identical direction):
//   gemm1:  x @ W1              -> bufA
//   agg :   relu(max-agg(bufA)+b1) -> bufB
//   gemm2:  bufB @ W2           -> bufA
//   agg :   relu(max-agg(bufA)+b2) -> bufB
//   head :  bufB @ We + be      -> out
extern "C" void kernel_launch(void* const* d_in, const int* in_sizes, int n_in,
                              void* d_out, int out_size) {
    const float* x  = (const float*)d_in[0];
    const int*   ei = (const int*)d_in[1];     // int32 (JAX x64 disabled)
    const float* ew = (const float*)d_in[2];
    const float* W1 = (const float*)d_in[3];
    const float* b1 = (const float*)d_in[4];
    const float* W2 = (const float*)d_in[5];
    const float* b2 = (const float*)d_in[6];
    const float* We = (const float*)d_in[7];
    const float* be = (const float*)d_in[8];
    float* out = (float*)d_out;

    const int TB = 256;
    int gN = (N_NODES + TB - 1) / TB;
    int gE = (N_EDGES + TB - 1) / TB;

    // graph structure (shared by both layers)
    zero_kernel<<<gN, TB>>>();
    deg_kernel<<<gE, TB>>>(ei, ew);
    dis_kernel<<<gN, TB>>>();
    scan_kernel<<<1, 1024>>>();
    fill_kernel<<<gE, TB>>>(ei, ew);

    // layer 1
    gemm1_kernel<<<(N_NODES * F_HID + TB - 1) / TB, TB>>>(x, W1);
    agg_kernel<<<N_NODES, TB>>>(b1);

    // layer 2
    {
        dim3 grid((N_NODES + 127) / 128, F_HID / 80);
        gemm_kernel<0><<<grid, 256>>>(W2, nullptr, nullptr, N_NODES, F_HID, F_HID);
    }
    agg_kernel<<<N_NODES, TB>>>(b2);

    // head
    {
        dim3 grid((N_NODES + 127) / 128, F_OUT / 80);
        gemm_kernel<1><<<grid, 256>>>(We, be, out, N_NODES, F_OUT, F_HID);
    }
}

// round 5
// speedup vs baseline: 1.2797x; 1.2797x over previous
#include <cuda_runtime.h>
#include <cuda_bf16.h>
#include <float.h>

#define N_NODES 50000
#define N_EDGES 1600000
#define F_HID   240
#define F_OUT   80
#define SCAN_B  256
#define SCAN_G  ((N_NODES + SCAN_B - 1) / SCAN_B)   // 196

// ---------------- scratch (device globals; no allocation allowed) ----------
__device__ float g_deg[N_NODES];
__device__ float g_dis[N_NODES];
__device__ int   g_cnt[N_NODES];
__device__ int   g_off[N_NODES];
__device__ int   g_cur[N_NODES];
__device__ int   g_blksum[SCAN_G];
__device__ int   g_blkoff[SCAN_G];
__device__ int2  g_edge[N_EDGES];                   // (src, nrm bits) packed
__device__ float g_bufA[(size_t)N_NODES * F_HID];   // GEMM outputs (pre-agg)
__device__ float g_bufB[(size_t)N_NODES * F_HID];   // agg outputs (post-relu)

// ---------------- graph preprocessing --------------------------------------
__global__ void zero_kernel() {
    int i = blockIdx.x * blockDim.x + threadIdx.x;
    if (i < N_NODES) { g_deg[i] = 0.0f; g_cnt[i] = 0; }
}

__global__ void deg_kernel(const int* __restrict__ ei,
                           const float* __restrict__ ew) {
    int e = blockIdx.x * blockDim.x + threadIdx.x;
    if (e < N_EDGES) {
        int c = ei[N_EDGES + e];
        if ((unsigned)c < N_NODES) {
            atomicAdd(&g_deg[c], ew[e]);
            atomicAdd(&g_cnt[c], 1);
        }
    }
}

__global__ void dis_kernel() {
    int i = blockIdx.x * blockDim.x + threadIdx.x;
    if (i < N_NODES) g_dis[i] = rsqrtf(g_deg[i] + 1.0f);  // +1 = self loop
}

// ---- parallel exclusive scan of g_cnt -> g_off / g_cur (3 phases) ---------
__global__ void scan1_kernel() {   // per-block sums
    __shared__ int s[SCAN_B];
    int t = threadIdx.x;
    int i = blockIdx.x * SCAN_B + t;
    s[t] = (i < N_NODES) ? g_cnt[i] : 0;
    __syncthreads();
    for (int d = SCAN_B / 2; d > 0; d >>= 1) {
        if (t < d) s[t] += s[t + d];
        __syncthreads();
    }
    if (t == 0) g_blksum[blockIdx.x] = s[0];
}

__global__ void scan2_kernel() {   // 1 block: exclusive scan of 196 block sums
    __shared__ int s[SCAN_B];
    int t = threadIdx.x;
    int v = (t < SCAN_G) ? g_blksum[t] : 0;
    s[t] = v;
    __syncthreads();
    for (int d = 1; d < SCAN_B; d <<= 1) {
        int u = (t >= d) ? s[t - d] : 0;
        __syncthreads();
        s[t] += u;
        __syncthreads();
    }
    if (t < SCAN_G) g_blkoff[t] = s[t] - v;
}

__global__ void scan3_kernel() {   // per-block exclusive scan + block offset
    __shared__ int s[SCAN_B];
    int t = threadIdx.x;
    int i = blockIdx.x * SCAN_B + t;
    int v = (i < N_NODES) ? g_cnt[i] : 0;
    s[t] = v;
    __syncthreads();
    for (int d = 1; d < SCAN_B; d <<= 1) {
        int u = (t >= d) ? s[t - d] : 0;
        __syncthreads();
        s[t] += u;
        __syncthreads();
    }
    if (i < N_NODES) {
        int excl = s[t] - v + g_blkoff[blockIdx.x];
        g_off[i] = excl;
        g_cur[i] = excl;
    }
}

__global__ void fill_kernel(const int* __restrict__ ei,
                            const float* __restrict__ ew) {
    int e = blockIdx.x * blockDim.x + threadIdx.x;
    if (e < N_EDGES) {
        int r = ei[e];
        int c = ei[N_EDGES + e];
        if ((unsigned)r < N_NODES && (unsigned)c < N_NODES) {
            float nrm = g_dis[r] * ew[e] * g_dis[c];
            int p = atomicAdd(&g_cur[c], 1);
            g_edge[p] = make_int2(r, __float_as_int(nrm));
        }
    }
}

// ---------------- GEMM1: [N,5] @ [5,240] -> g_bufA -------------------------
__global__ void gemm1_kernel(const float* __restrict__ x,
                             const float* __restrict__ W1) {
    int idx = blockIdx.x * blockDim.x + threadIdx.x;
    if (idx >= N_NODES * F_HID) return;
    int n = idx / F_HID, f = idx - n * F_HID;
    const float* xr = x + n * 5;
    float acc = 0.0f;
#pragma unroll
    for (int k = 0; k < 5; k++) acc = fmaf(xr[k], W1[k * F_HID + f], acc);
    g_bufA[idx] = acc;
}

// ---------------- scatter-max aggregation (CSR, float4 gathers) -------------
// Reads g_bufA, writes relu(max-agg + bias) to g_bufB.
// 256 threads/node: 4 edge-groups x 64 lanes (60 active, one float4 each).
__global__ void agg_kernel(const float* __restrict__ bias) {
    const float4* __restrict__ h4   = (const float4*)g_bufA;   // stride 60
    float4* __restrict__       out4 = (float4*)g_bufB;
    int n   = blockIdx.x;
    int tid = threadIdx.x;
    int grp = tid >> 6;        // 0..3
    int f4  = tid & 63;        // 0..63, active if < 60

    __shared__ int2   s_e[128];
    __shared__ float4 s_red[4][60];

    float d     = g_dis[n];
    int   start = g_off[n];
    int   cnt   = g_cnt[n];

    float4 v = make_float4(-FLT_MAX, -FLT_MAX, -FLT_MAX, -FLT_MAX);

    for (int base = 0; base < cnt; base += 128) {
        int m = min(128, cnt - base);
        __syncthreads();
        if (tid < m) s_e[tid] = g_edge[start + base + tid];
        __syncthreads();
        if (f4 < 60) {
            for (int e = grp; e < m; e += 4) {
                int2  ed  = s_e[e];
                float nrm = __int_as_float(ed.y);
                float4 hv = h4[(size_t)ed.x * 60 + f4];
                v.x = fmaxf(v.x, nrm * hv.x);
                v.y = fmaxf(v.y, nrm * hv.y);
                v.z = fmaxf(v.z, nrm * hv.z);
                v.w = fmaxf(v.w, nrm * hv.w);
            }
        }
    }
    if (f4 < 60) s_red[grp][f4] = v;
    __syncthreads();

    if (tid < 60) {
        float4 a = s_red[0][tid], b = s_red[1][tid];
        float4 c = s_red[2][tid], e = s_red[3][tid];
        float4 m4;
        m4.x = fmaxf(fmaxf(a.x, b.x), fmaxf(c.x, e.x));
        m4.y = fmaxf(fmaxf(a.y, b.y), fmaxf(c.y, e.y));
        m4.z = fmaxf(fmaxf(a.z, b.z), fmaxf(c.z, e.z));
        m4.w = fmaxf(fmaxf(a.w, b.w), fmaxf(c.w, e.w));
        // self-loop term: dis[n]^2 * h[n]
        float  dd = d * d;
        float4 hv = h4[(size_t)n * 60 + tid];
        m4.x = fmaxf(m4.x, dd * hv.x);
        m4.y = fmaxf(m4.y, dd * hv.y);
        m4.z = fmaxf(m4.z, dd * hv.z);
        m4.w = fmaxf(m4.w, dd * hv.w);
        float4 bi = ((const float4*)bias)[tid];
        m4.x = fmaxf(m4.x + bi.x, 0.0f);
        m4.y = fmaxf(m4.y + bi.y, 0.0f);
        m4.z = fmaxf(m4.z + bi.z, 0.0f);
        m4.w = fmaxf(m4.w + bi.w, 0.0f);
        out4[(size_t)n * 60 + tid] = m4;
    }
}

// ---------------- tiled SGEMM: C[M,Nn] = g_bufB[M,K] @ B[K,Nn] (+bias) -----
// BM=128, BN=80, BK=16, 256 threads, 8x5 micro-tile
template <int DST>  // 0: C = g_bufA ; 1: C = Cout (harness output)
__global__ void gemm_kernel(const float* __restrict__ B,
                            const float* __restrict__ bias,
                            float* __restrict__ Cout,
                            int M, int Nn, int K) {
    const float* __restrict__ A = g_bufB;
    float* __restrict__ C = DST == 0 ? g_bufA : Cout;

    __shared__ float As[16][129];
    __shared__ float Bs[16][80];

    int tid = threadIdx.x;
    int ty = tid / 16, tx = tid % 16;
    int m0 = blockIdx.x * 128;
    int n0 = blockIdx.y * 80;

    float acc[8][5];
#pragma unroll
    for (int i = 0; i < 8; i++)
#pragma unroll
        for (int j = 0; j < 5; j++) acc[i][j] = 0.0f;

    for (int k0 = 0; k0 < K; k0 += 16) {
#pragma unroll
        for (int i = 0; i < 8; i++) {
            int l = tid + i * 256;        // 0..2047
            int r = l >> 4, c = l & 15;
            int row = m0 + r;
            row = row < M ? row : M - 1;
            As[c][r] = A[(size_t)row * K + k0 + c];
        }
#pragma unroll
        for (int i = 0; i < 5; i++) {
            int l = tid + i * 256;        // 0..1279
            int r = l / 80, c = l - r * 80;
            Bs[r][c] = B[(size_t)(k0 + r) * Nn + n0 + c];
        }
        __syncthreads();
#pragma unroll
        for (int kk = 0; kk < 16; kk++) {
            float a[8], b[5];
#pragma unroll
            for (int i = 0; i < 8; i++) a[i] = As[kk][ty * 8 + i];
#pragma unroll
            for (int j = 0; j < 5; j++) b[j] = Bs[kk][tx * 5 + j];
#pragma unroll
            for (int i = 0; i < 8; i++)
#pragma unroll
                for (int j = 0; j < 5; j++) acc[i][j] = fmaf(a[i], b[j], acc[i][j]);
        }
        __syncthreads();
    }

#pragma unroll
    for (int i = 0; i < 8; i++) {
        int row = m0 + ty * 8 + i;
        if (row < M) {
#pragma unroll
            for (int j = 0; j < 5; j++) {
                int col = n0 + tx * 5 + j;
                float v = acc[i][j];
                if (bias) v += bias[col];
                C[(size_t)row * Nn + col] = v;
            }
        }
    }
}

// ---------------- launch ----------------------------------------------------
// Dataflow:
//   gemm1:  x @ W1                 -> bufA
//   agg :   relu(max-agg(bufA)+b1) -> bufB
//   gemm2:  bufB @ W2              -> bufA
//   agg :   relu(max-agg(bufA)+b2) -> bufB
//   head :  bufB @ We + be         -> out
extern "C" void kernel_launch(void* const* d_in, const int* in_sizes, int n_in,
                              void* d_out, int out_size) {
    const float* x  = (const float*)d_in[0];
    const int*   ei = (const int*)d_in[1];     // int32 (JAX x64 disabled)
    const float* ew = (const float*)d_in[2];
    const float* W1 = (const float*)d_in[3];
    const float* b1 = (const float*)d_in[4];
    const float* W2 = (const float*)d_in[5];
    const float* b2 = (const float*)d_in[6];
    const float* We = (const float*)d_in[7];
    const float* be = (const float*)d_in[8];
    float* out = (float*)d_out;

    const int TB = 256;
    int gN = (N_NODES + TB - 1) / TB;
    int gE = (N_EDGES + TB - 1) / TB;

    // graph structure (shared by both layers)
    zero_kernel<<<gN, TB>>>();
    deg_kernel<<<gE, TB>>>(ei, ew);
    dis_kernel<<<gN, TB>>>();
    scan1_kernel<<<SCAN_G, SCAN_B>>>();
    scan2_kernel<<<1, SCAN_B>>>();
    scan3_kernel<<<SCAN_G, SCAN_B>>>();
    fill_kernel<<<gE, TB>>>(ei, ew);

    // layer 1
    gemm1_kernel<<<(N_NODES * F_HID + TB - 1) / TB, TB>>>(x, W1);
    agg_kernel<<<N_NODES, TB>>>(b1);

    // layer 2
    {
        dim3 grid((N_NODES + 127) / 128, F_HID / 80);
        gemm_kernel<0><<<grid, 256>>>(W2, nullptr, nullptr, N_NODES, F_HID, F_HID);
    }
    agg_kernel<<<N_NODES, TB>>>(b2);

    // head
    {
        dim3 grid((N_NODES + 127) / 128, F_OUT / 80);
        gemm_kernel<1><<<grid, 256>>>(We, be, out, N_NODES, F_OUT, F_HID);
    }
}